// round 6
// baseline (speedup 1.0000x reference)
#include <cuda_runtime.h>
#include <cuda_bf16.h>
#include <math.h>
#include <stdint.h>

#define BB 4
#define SS 1024
#define EE 512
#define HH 512
#define VV 32000
#define NHH 8
#define HD 64
#define EPSL 1e-5f

// ---------------- scratch (device globals; no allocation allowed) ----------------
__device__ float g_x[BB * SS * HH];
__device__ float g_I[BB * SS * HH];
__device__ float g_act[BB * SS * HH];
__device__ float g_qkv[BB * SS * 3 * HH];
__device__ float g_o[BB * SS * HH];
// tf32-rounded weights
__device__ float g_w0[HH * EE];
__device__ float g_w1[HH * HH];
__device__ float g_win[3 * HH * HH];
__device__ float g_wo[HH * HH];
__device__ float g_wout[VV * HH];

__device__ __forceinline__ uint32_t f2tf32(float x) {
    uint32_t r;
    asm("cvt.rna.tf32.f32 %0, %1;" : "=r"(r) : "f"(x));
    return r;
}
__device__ __forceinline__ float roundtf(float x) { return __uint_as_float(f2tf32(x)); }

// ---------------- tf32 tensor-core GEMM (mma.sync) ----------------
// C[M,N] = A[M,K] * W[N,K]^T + bias[N]
// block tile 128x128, BK=64, 256 threads (8 warps), warp tile 64x32, 2 CTAs/SM.
// Inputs MUST already be tf32-rounded (HW truncation is then exact).
// dynamic smem: A 8192 u32 (32KB) + B 8192 u32 (32KB) = 64KB, single-buffered.
#define GEMM_SMEM (64 * 1024)

__global__ __launch_bounds__(256, 2) void gemm_tf32(
    const float* __restrict__ A, const float* __restrict__ W,
    const float* __restrict__ bias, float* __restrict__ C,
    int M, int N, int K, int round_out) {
    extern __shared__ uint32_t sm[];
    uint32_t* As = sm;          // [8192]
    uint32_t* Bs = sm + 8192;   // [8192]

    const int tid = threadIdx.x;
    const int lane = tid & 31;
    const int wid = tid >> 5;
    const int warp_m = wid & 1;        // 0..1  (64 rows each)
    const int warp_n = wid >> 1;       // 0..3  (32 cols each)
    const int bm = blockIdx.x * 128;   // M-tile fastest => weight-tile reuse in a wave
    const int bn = blockIdx.y * 128;

    float c[4][4][4];
#pragma unroll
    for (int mt = 0; mt < 4; mt++)
#pragma unroll
        for (int nt = 0; nt < 4; nt++)
#pragma unroll
            for (int q = 0; q < 4; q++) c[mt][nt][q] = 0.f;

    const int arow = tid >> 4;          // 0..15
    const int acol = (tid & 15) * 4;    // k offset 0..60

    // fragment-order smem scatter addresses (same element mapping as round 2,
    // extended to BK=64: kk = acol>>3 in 0..7)
    int a_addr[8], b_addr[8];
#pragma unroll
    for (int p = 0; p < 8; p++) {
        int grow = arow + p * 16;      // 0..127
        int r = grow & 15;
        int m16 = grow >> 4;
        int tileA = (acol >> 3) * 8 + m16;
        a_addr[p] = tileA * 128 + ((r & 7) * 4) * 4 + ((r >> 3) + 2 * ((acol >> 2) & 1));
        int rn = grow & 7;
        int n8 = grow >> 3;
        int tileB = (acol >> 3) * 16 + n8;
        b_addr[p] = tileB * 64 + (rn * 4) * 2 + ((acol >> 2) & 1);
    }

    const float* Ab = A + (size_t)bm * K + acol;
    const float* Wb = W + (size_t)bn * K + acol;
    const int nchunk = K >> 6;   // BK=64

    for (int s = 0; s < nchunk; ++s) {
        const float* Ac = Ab + s * 64;
        const float* Wc = Wb + s * 64;
        float4 av[8], wv[8];
#pragma unroll
        for (int p = 0; p < 8; p++) {
            av[p] = *(const float4*)(Ac + (size_t)(arow + p * 16) * K);
            wv[p] = *(const float4*)(Wc + (size_t)(arow + p * 16) * K);
        }
        __syncthreads();   // all warps done reading previous chunk
#pragma unroll
        for (int p = 0; p < 8; p++) {
            As[a_addr[p] + 0]  = __float_as_uint(av[p].x);
            As[a_addr[p] + 4]  = __float_as_uint(av[p].y);
            As[a_addr[p] + 8]  = __float_as_uint(av[p].z);
            As[a_addr[p] + 12] = __float_as_uint(av[p].w);
            Bs[b_addr[p] + 0]  = __float_as_uint(wv[p].x);
            Bs[b_addr[p] + 2]  = __float_as_uint(wv[p].y);
            Bs[b_addr[p] + 4]  = __float_as_uint(wv[p].z);
            Bs[b_addr[p] + 6]  = __float_as_uint(wv[p].w);
        }
        __syncthreads();

#pragma unroll
        for (int kk = 0; kk < 8; kk++) {
            uint4 af[4];
            uint2 bf[4];
#pragma unroll
            for (int mt = 0; mt < 4; mt++)
                af[mt] = *(const uint4*)&As[(kk * 8 + warp_m * 4 + mt) * 128 + lane * 4];
#pragma unroll
            for (int nt = 0; nt < 4; nt++)
                bf[nt] = *(const uint2*)&Bs[(kk * 16 + warp_n * 4 + nt) * 64 + lane * 2];
#pragma unroll
            for (int mt = 0; mt < 4; mt++)
#pragma unroll
                for (int nt = 0; nt < 4; nt++) {
                    asm volatile(
                        "mma.sync.aligned.m16n8k8.row.col.f32.tf32.tf32.f32 "
                        "{%0,%1,%2,%3}, {%4,%5,%6,%7}, {%8,%9}, {%0,%1,%2,%3};"
                        : "+f"(c[mt][nt][0]), "+f"(c[mt][nt][1]),
                          "+f"(c[mt][nt][2]), "+f"(c[mt][nt][3])
                        : "r"(af[mt].x), "r"(af[mt].y), "r"(af[mt].z), "r"(af[mt].w),
                          "r"(bf[nt].x), "r"(bf[nt].y));
                }
        }
    }

    // epilogue
    const int g = lane >> 2;
    const int t4 = lane & 3;
#pragma unroll
    for (int mt = 0; mt < 4; mt++) {
        int row0 = bm + warp_m * 64 + mt * 16 + g;
#pragma unroll
        for (int nt = 0; nt < 4; nt++) {
            int col = bn + warp_n * 32 + nt * 8 + t4 * 2;
            float b0 = bias[col], b1 = bias[col + 1];
            float2 v0 = make_float2(c[mt][nt][0] + b0, c[mt][nt][1] + b1);
            float2 v1 = make_float2(c[mt][nt][2] + b0, c[mt][nt][3] + b1);
            if (round_out) {
                v0.x = roundtf(v0.x); v0.y = roundtf(v0.y);
                v1.x = roundtf(v1.x); v1.y = roundtf(v1.y);
            }
            *(float2*)(C + (size_t)row0 * N + col) = v0;
            *(float2*)(C + (size_t)(row0 + 8) * N + col) = v1;
        }
    }
}

// ---------------- weight rounding ----------------
__global__ void round_tf32_kernel(const float* __restrict__ in, float* __restrict__ out, int n4) {
    int i = blockIdx.x * blockDim.x + threadIdx.x;
    if (i >= n4) return;
    float4 v = ((const float4*)in)[i];
    v.x = roundtf(v.x); v.y = roundtf(v.y); v.z = roundtf(v.z); v.w = roundtf(v.w);
    ((float4*)out)[i] = v;
}

// ---------------- embed + positional encoding (tf32-rounded out) ----------------
__global__ void embed_pos_kernel(const int* __restrict__ tokens,
                                 const float* __restrict__ emb,
                                 float* __restrict__ x) {
    int idx = blockIdx.x * blockDim.x + threadIdx.x;
    if (idx >= BB * SS * EE) return;
    int e = idx & (EE - 1);
    int bs = idx / EE;
    int s = bs & (SS - 1);
    int tok = tokens[bs];
    int i2 = (e >> 1) << 1;
    float div = expf(-(float)i2 * (9.210340371976184f / (float)EE));
    float arg = (float)s * div;
    float pe = (e & 1) ? cosf(arg) : sinf(arg);
    x[idx] = roundtf(emb[(size_t)tok * EE + e] + pe);
}

// ---------------- liquid scan ----------------
__global__ void liquid_scan_kernel(const float* __restrict__ I,
                                   const float* __restrict__ tau,
                                   const float* __restrict__ log_dt,
                                   float* __restrict__ out) {
    int idx = blockIdx.x * blockDim.x + threadIdx.x;
    if (idx >= BB * HH) return;
    int b = idx / HH, h = idx & (HH - 1);
    float dt = expf(log_dt[0]);
    float a = dt / tau[h];
    float u = 0.f, s = 0.f;
    const float* Ip = I + (size_t)b * SS * HH + h;
    float* op = out + (size_t)b * SS * HH + h;
    for (int t = 0; t < SS; t += 8) {
        float It[8];
#pragma unroll
        for (int q = 0; q < 8; q++) It[q] = Ip[(size_t)(t + q) * HH];
#pragma unroll
        for (int q = 0; q < 8; q++) {
            float un = u + a * (It[q] - u);
            float sn = s + a * (u - s);
            u = un; s = sn;
            op[(size_t)(t + q) * HH] = tanhf(sn);
        }
    }
}

// ---------------- layernorm (tf32-rounded out) ----------------
__global__ __launch_bounds__(256) void layernorm_kernel(
    const float* __restrict__ in, const float* __restrict__ g,
    const float* __restrict__ beta, float* __restrict__ out) {
    int row = blockIdx.x * 8 + (threadIdx.x >> 5);
    int lane = threadIdx.x & 31;
    const float* p = in + (size_t)row * HH;
    float sum = 0.f, sq = 0.f;
#pragma unroll
    for (int i = 0; i < HH / 32; i++) {
        float v = p[lane + i * 32];
        sum += v; sq += v * v;
    }
#pragma unroll
    for (int o = 16; o; o >>= 1) {
        sum += __shfl_xor_sync(0xffffffffu, sum, o);
        sq  += __shfl_xor_sync(0xffffffffu, sq, o);
    }
    float mu = sum * (1.0f / HH);
    float var = sq * (1.0f / HH) - mu * mu;
    float inv = rsqrtf(var + EPSL);
    float* q = out + (size_t)row * HH;
#pragma unroll
    for (int i = 0; i < HH / 32; i++) {
        int c = lane + i * 32;
        q[c] = roundtf(g[c] * (p[c] - mu) * inv + beta[c]);
    }
}

// ---------------- attention (flash-style, tf32-rounded out) ----------------
__global__ __launch_bounds__(128) void attention_kernel(
    const float* __restrict__ qkv, float* __restrict__ o) {
    const int qt = blockIdx.x;
    const int h = blockIdx.y;
    const int b = blockIdx.z;
    __shared__ float Qs[32][HD + 1];
    __shared__ float Kst[HD][64];
    __shared__ float Vs[64][HD];
    const int tid = threadIdx.x;
    const int r = tid >> 2;
    const int part = tid & 3;
    const int lane = tid & 31;
    const size_t base = (size_t)b * SS * 3 * HH;

    for (int i = tid; i < 32 * 16; i += 128) {
        int row = i >> 4, d4 = (i & 15) * 4;
        float4 v = *(const float4*)(qkv + base + (size_t)(qt * 32 + row) * 3 * HH + h * HD + d4);
        Qs[row][d4 + 0] = v.x; Qs[row][d4 + 1] = v.y;
        Qs[row][d4 + 2] = v.z; Qs[row][d4 + 3] = v.w;
    }

    float acc[16];
#pragma unroll
    for (int i = 0; i < 16; i++) acc[i] = 0.f;
    float m = -1e30f, l = 0.f;

    for (int kt = 0; kt < SS; kt += 64) {
        __syncthreads();
        for (int i = tid; i < 64 * 16; i += 128) {
            int row = i >> 4, d4 = (i & 15) * 4;
            const float* kp = qkv + base + (size_t)(kt + row) * 3 * HH + HH + h * HD + d4;
            float4 kv = *(const float4*)kp;
            Kst[d4 + 0][row] = kv.x; Kst[d4 + 1][row] = kv.y;
            Kst[d4 + 2][row] = kv.z; Kst[d4 + 3][row] = kv.w;
            *(float4*)&Vs[row][d4] = *(const float4*)(kp + HH);
        }
        __syncthreads();

        float sc[16];
#pragma unroll
        for (int jj = 0; jj < 16; jj++) sc[jj] = 0.f;
        for (int d = 0; d < HD; ++d) {
            float qv = Qs[r][d];
            const float* kr = &Kst[d][part * 16];
#pragma unroll
            for (int jj = 0; jj < 16; jj++) sc[jj] += qv * kr[jj];
        }
        float tmax = -1e30f;
#pragma unroll
        for (int jj = 0; jj < 16; jj++) { sc[jj] *= 0.125f; tmax = fmaxf(tmax, sc[jj]); }
        tmax = fmaxf(tmax, __shfl_xor_sync(0xffffffffu, tmax, 1));
        tmax = fmaxf(tmax, __shfl_xor_sync(0xffffffffu, tmax, 2));
        float mnew = fmaxf(m, tmax);
        float corr = __expf(m - mnew);
        float pl[16];
        float psum = 0.f;
#pragma unroll
        for (int jj = 0; jj < 16; jj++) { pl[jj] = __expf(sc[jj] - mnew); psum += pl[jj]; }
        psum += __shfl_xor_sync(0xffffffffu, psum, 1);
        psum += __shfl_xor_sync(0xffffffffu, psum, 2);
        l = l * corr + psum;
        m = mnew;
#pragma unroll
        for (int i = 0; i < 16; i++) acc[i] *= corr;
#pragma unroll
        for (int src = 0; src < 4; ++src) {
#pragma unroll
            for (int jj = 0; jj < 16; jj++) {
                float p = __shfl_sync(0xffffffffu, pl[jj], (lane & ~3) | src);
                const float* vr = &Vs[src * 16 + jj][part * 16];
#pragma unroll
                for (int dd = 0; dd < 16; dd++) acc[dd] += p * vr[dd];
            }
        }
    }
    float linv = 1.f / l;
    float* op = o + (size_t)(b * SS + qt * 32 + r) * HH + h * HD + part * 16;
#pragma unroll
    for (int dd = 0; dd < 16; dd++) op[dd] = roundtf(acc[dd] * linv);
}

// ---------------- launch ----------------
extern "C" void kernel_launch(void* const* d_in, const int* in_sizes, int n_in,
                              void* d_out, int out_size) {
    const int*   tokens = (const int*)d_in[0];
    const float* emb    = (const float*)d_in[1];
    const float* W0     = (const float*)d_in[2];
    const float* b0     = (const float*)d_in[3];
    const float* tau0   = (const float*)d_in[4];
    const float* g0     = (const float*)d_in[5];
    const float* be0    = (const float*)d_in[6];
    const float* W1     = (const float*)d_in[7];
    const float* b1     = (const float*)d_in[8];
    const float* tau1   = (const float*)d_in[9];
    const float* g1     = (const float*)d_in[10];
    const float* be1    = (const float*)d_in[11];
    const float* w_in   = (const float*)d_in[12];
    const float* b_in   = (const float*)d_in[13];
    const float* w_o    = (const float*)d_in[14];
    const float* b_o    = (const float*)d_in[15];
    const float* Wout   = (const float*)d_in[16];
    const float* bout   = (const float*)d_in[17];
    const float* log_dt = (const float*)d_in[18];
    float* out = (float*)d_out;

    float *px, *pI, *pact, *pqkv, *po, *pw0, *pw1, *pwin, *pwo, *pwout;
    cudaGetSymbolAddress((void**)&px,    g_x);
    cudaGetSymbolAddress((void**)&pI,    g_I);
    cudaGetSymbolAddress((void**)&pact,  g_act);
    cudaGetSymbolAddress((void**)&pqkv,  g_qkv);
    cudaGetSymbolAddress((void**)&po,    g_o);
    cudaGetSymbolAddress((void**)&pw0,   g_w0);
    cudaGetSymbolAddress((void**)&pw1,   g_w1);
    cudaGetSymbolAddress((void**)&pwin,  g_win);
    cudaGetSymbolAddress((void**)&pwo,   g_wo);
    cudaGetSymbolAddress((void**)&pwout, g_wout);

    cudaFuncSetAttribute(gemm_tf32, cudaFuncAttributeMaxDynamicSharedMemorySize, GEMM_SMEM);

    const int M = BB * SS;  // 4096

    // round weights to tf32 once per launch (HW truncation then exact)
    round_tf32_kernel<<<(HH * EE / 4 + 255) / 256, 256>>>(W0, pw0, HH * EE / 4);
    round_tf32_kernel<<<(HH * HH / 4 + 255) / 256, 256>>>(W1, pw1, HH * HH / 4);
    round_tf32_kernel<<<(3 * HH * HH / 4 + 255) / 256, 256>>>(w_in, pwin, 3 * HH * HH / 4);
    round_tf32_kernel<<<(HH * HH / 4 + 255) / 256, 256>>>(w_o, pwo, HH * HH / 4);
    round_tf32_kernel<<<(VV * HH / 4 + 255) / 256, 256>>>(Wout, pwout, VV * HH / 4);

    embed_pos_kernel<<<(BB * SS * EE) / 256, 256>>>(tokens, emb, px);

    gemm_tf32<<<dim3(M / 128, HH / 128), 256, GEMM_SMEM>>>(px, pw0, b0, pI, M, HH, EE, 0);
    liquid_scan_kernel<<<(BB * HH + 255) / 256, 256>>>(pI, tau0, log_dt, pact);
    layernorm_kernel<<<M / 8, 256>>>(pact, g0, be0, px);

    gemm_tf32<<<dim3(M / 128, HH / 128), 256, GEMM_SMEM>>>(px, pw1, b1, pI, M, HH, HH, 0);
    liquid_scan_kernel<<<(BB * HH + 255) / 256, 256>>>(pI, tau1, log_dt, pact);
    layernorm_kernel<<<M / 8, 256>>>(pact, g1, be1, px);

    gemm_tf32<<<dim3(M / 128, 3 * HH / 128), 256, GEMM_SMEM>>>(px, pwin, b_in, pqkv, M, 3 * HH, HH, 0);
    attention_kernel<<<dim3(SS / 32, NHH, BB), 128>>>(pqkv, po);
    gemm_tf32<<<dim3(M / 128, HH / 128), 256, GEMM_SMEM>>>(po, pwo, b_o, px, M, HH, HH, 1);

    gemm_tf32<<<dim3(M / 128, VV / 128), 256, GEMM_SMEM>>>(px, pwout, bout, out, M, VV, HH, 0);
}

// round 7
// speedup vs baseline: 1.1508x; 1.1508x over previous
#include <cuda_runtime.h>
#include <cuda_bf16.h>
#include <math.h>
#include <stdint.h>

#define BB 4
#define SS 1024
#define EE 512
#define HH 512
#define VV 32000
#define NHH 8
#define HD 64
#define EPSL 1e-5f

// ---------------- scratch (device globals; no allocation allowed) ----------------
__device__ float g_x[BB * SS * HH];
__device__ float g_I[BB * SS * HH];
__device__ float g_act[BB * SS * HH];
__device__ float g_qkv[BB * SS * 3 * HH];
__device__ float g_o[BB * SS * HH];
// tf32-rounded weights
__device__ float g_w0[HH * EE];
__device__ float g_w1[HH * HH];
__device__ float g_win[3 * HH * HH];
__device__ float g_wo[HH * HH];
__device__ float g_wout[VV * HH];

__device__ __forceinline__ uint32_t f2tf32(float x) {
    uint32_t r;
    asm("cvt.rna.tf32.f32 %0, %1;" : "=r"(r) : "f"(x));
    return r;
}
__device__ __forceinline__ float roundtf(float x) { return __uint_as_float(f2tf32(x)); }
__device__ __forceinline__ uint32_t smem_u32(const void* p) {
    uint32_t a;
    asm("{ .reg .u64 t; cvta.to.shared.u64 t, %1; cvt.u32.u64 %0, t; }" : "=r"(a) : "l"(p));
    return a;
}

// ---------------- tf32 tensor-core GEMM (mma.sync + cp.async 3-stage pipeline) ----
// C[M,N] = A[M,K] * W[N,K]^T + bias[N]
// block tile 128x128, BK=32, 256 threads (8 warps), warp tile 64x32.
// Inputs MUST already be tf32-rounded (HW truncation is then exact).
// Stage = A tile 16KB + B tile 16KB = 32KB; 3 stages = 96KB dynamic smem.
#define GSTAGES 3
#define STAGE_U32 8192
#define GEMM_SMEM (GSTAGES * STAGE_U32 * 4)

__global__ __launch_bounds__(256) void gemm_tf32(
    const float* __restrict__ A, const float* __restrict__ W,
    const float* __restrict__ bias, float* __restrict__ C,
    int M, int N, int K, int round_out) {
    extern __shared__ uint32_t sm[];
    const uint32_t sbase = smem_u32(sm);

    const int tid = threadIdx.x;
    const int lane = tid & 31;
    const int wid = tid >> 5;
    const int warp_m = wid & 1;        // 0..1  (64 rows each)
    const int warp_n = wid >> 1;       // 0..3  (32 cols each)
    const int bm = blockIdx.x * 128;   // M-tile fastest => W-tile reuse within a wave
    const int bn = blockIdx.y * 128;

    float c[4][4][4];
#pragma unroll
    for (int mt = 0; mt < 4; mt++)
#pragma unroll
        for (int nt = 0; nt < 4; nt++)
#pragma unroll
            for (int q = 0; q < 4; q++) c[mt][nt][q] = 0.f;

    // cp.async: instruction j copies gmem row (j*8 + wid), float index = lane,
    // into fragment-ordered smem (same element mapping validated in round 2).
    // dst closed forms (u32 index):
    //   A: (lane>>3)*1024 + wid*16 + 2*((lane>>2)&1) + 4*(lane&3)  + (j>>1)*128 + (j&1)
    //   B: (lane>>3)*1024 + wid*8  + ((lane>>2)&1)   + 2*(lane&3)  + j*64
    const uint32_t CA4 = ((lane >> 3) * 1024 + wid * 16 + 2 * ((lane >> 2) & 1) + 4 * (lane & 3)) * 4;
    const uint32_t CB4 = ((lane >> 3) * 1024 + wid * 8 + ((lane >> 2) & 1) + 2 * (lane & 3)) * 4 + 16384;

    const float* Abase = A + (size_t)(bm + wid) * K + lane;
    const float* Wbase = W + (size_t)(bn + wid) * K + lane;
    const int nchunk = K >> 5;  // BK=32

    auto issue = [&](int s) {
        const int buf = s % GSTAGES;
        const uint32_t sA = sbase + buf * (STAGE_U32 * 4) + CA4;
        const uint32_t sB = sbase + buf * (STAGE_U32 * 4) + CB4;
        const float* ga = Abase + s * 32;
        const float* gw = Wbase + s * 32;
#pragma unroll
        for (int j = 0; j < 16; j++) {
            asm volatile("cp.async.ca.shared.global [%0], [%1], 4;"
                         :: "r"(sA + ((j >> 1) * 128 + (j & 1)) * 4), "l"(ga + (size_t)j * 8 * K));
            asm volatile("cp.async.ca.shared.global [%0], [%1], 4;"
                         :: "r"(sB + j * 64 * 4), "l"(gw + (size_t)j * 8 * K));
        }
    };

    issue(0);
    asm volatile("cp.async.commit_group;" ::: "memory");
    issue(1);
    asm volatile("cp.async.commit_group;" ::: "memory");

    for (int s = 0; s < nchunk; ++s) {
        asm volatile("cp.async.wait_group 1;" ::: "memory");
        __syncthreads();           // stage s ready for ALL warps; buffer (s%3) free to refill next iter
        if (s + 2 < nchunk) issue(s + 2);
        asm volatile("cp.async.commit_group;" ::: "memory");  // one group per iter (may be empty)

        const uint32_t* As = sm + (s % GSTAGES) * STAGE_U32;
        const uint32_t* Bs = As + 4096;
#pragma unroll
        for (int kk = 0; kk < 4; kk++) {
            uint4 af[4];
            uint2 bf[4];
#pragma unroll
            for (int mt = 0; mt < 4; mt++)
                af[mt] = *(const uint4*)&As[(kk * 8 + warp_m * 4 + mt) * 128 + lane * 4];
#pragma unroll
            for (int nt = 0; nt < 4; nt++)
                bf[nt] = *(const uint2*)&Bs[(kk * 16 + warp_n * 4 + nt) * 64 + lane * 2];
#pragma unroll
            for (int mt = 0; mt < 4; mt++)
#pragma unroll
                for (int nt = 0; nt < 4; nt++) {
                    asm volatile(
                        "mma.sync.aligned.m16n8k8.row.col.f32.tf32.tf32.f32 "
                        "{%0,%1,%2,%3}, {%4,%5,%6,%7}, {%8,%9}, {%0,%1,%2,%3};"
                        : "+f"(c[mt][nt][0]), "+f"(c[mt][nt][1]),
                          "+f"(c[mt][nt][2]), "+f"(c[mt][nt][3])
                        : "r"(af[mt].x), "r"(af[mt].y), "r"(af[mt].z), "r"(af[mt].w),
                          "r"(bf[nt].x), "r"(bf[nt].y));
                }
        }
    }

    // epilogue
    const int g = lane >> 2;
    const int t4 = lane & 3;
#pragma unroll
    for (int mt = 0; mt < 4; mt++) {
        int row0 = bm + warp_m * 64 + mt * 16 + g;
#pragma unroll
        for (int nt = 0; nt < 4; nt++) {
            int col = bn + warp_n * 32 + nt * 8 + t4 * 2;
            float b0 = bias[col], b1 = bias[col + 1];
            float2 v0 = make_float2(c[mt][nt][0] + b0, c[mt][nt][1] + b1);
            float2 v1 = make_float2(c[mt][nt][2] + b0, c[mt][nt][3] + b1);
            if (round_out) {
                v0.x = roundtf(v0.x); v0.y = roundtf(v0.y);
                v1.x = roundtf(v1.x); v1.y = roundtf(v1.y);
            }
            *(float2*)(C + (size_t)row0 * N + col) = v0;
            *(float2*)(C + (size_t)(row0 + 8) * N + col) = v1;
        }
    }
}

// ---------------- weight rounding ----------------
__global__ void round_tf32_kernel(const float* __restrict__ in, float* __restrict__ out, int n4) {
    int i = blockIdx.x * blockDim.x + threadIdx.x;
    if (i >= n4) return;
    float4 v = ((const float4*)in)[i];
    v.x = roundtf(v.x); v.y = roundtf(v.y); v.z = roundtf(v.z); v.w = roundtf(v.w);
    ((float4*)out)[i] = v;
}

// ---------------- embed + positional encoding (tf32-rounded out) ----------------
__global__ void embed_pos_kernel(const int* __restrict__ tokens,
                                 const float* __restrict__ emb,
                                 float* __restrict__ x) {
    int idx = blockIdx.x * blockDim.x + threadIdx.x;
    if (idx >= BB * SS * EE) return;
    int e = idx & (EE - 1);
    int bs = idx / EE;
    int s = bs & (SS - 1);
    int tok = tokens[bs];
    int i2 = (e >> 1) << 1;
    float div = expf(-(float)i2 * (9.210340371976184f / (float)EE));
    float arg = (float)s * div;
    float pe = (e & 1) ? cosf(arg) : sinf(arg);
    x[idx] = roundtf(emb[(size_t)tok * EE + e] + pe);
}

// ---------------- liquid scan ----------------
__global__ void liquid_scan_kernel(const float* __restrict__ I,
                                   const float* __restrict__ tau,
                                   const float* __restrict__ log_dt,
                                   float* __restrict__ out) {
    int idx = blockIdx.x * blockDim.x + threadIdx.x;
    if (idx >= BB * HH) return;
    int b = idx / HH, h = idx & (HH - 1);
    float dt = expf(log_dt[0]);
    float a = dt / tau[h];
    float u = 0.f, s = 0.f;
    const float* Ip = I + (size_t)b * SS * HH + h;
    float* op = out + (size_t)b * SS * HH + h;
    for (int t = 0; t < SS; t += 8) {
        float It[8];
#pragma unroll
        for (int q = 0; q < 8; q++) It[q] = Ip[(size_t)(t + q) * HH];
#pragma unroll
        for (int q = 0; q < 8; q++) {
            float un = u + a * (It[q] - u);
            float sn = s + a * (u - s);
            u = un; s = sn;
            op[(size_t)(t + q) * HH] = tanhf(sn);
        }
    }
}

// ---------------- layernorm (tf32-rounded out) ----------------
__global__ __launch_bounds__(256) void layernorm_kernel(
    const float* __restrict__ in, const float* __restrict__ g,
    const float* __restrict__ beta, float* __restrict__ out) {
    int row = blockIdx.x * 8 + (threadIdx.x >> 5);
    int lane = threadIdx.x & 31;
    const float* p = in + (size_t)row * HH;
    float sum = 0.f, sq = 0.f;
#pragma unroll
    for (int i = 0; i < HH / 32; i++) {
        float v = p[lane + i * 32];
        sum += v; sq += v * v;
    }
#pragma unroll
    for (int o = 16; o; o >>= 1) {
        sum += __shfl_xor_sync(0xffffffffu, sum, o);
        sq  += __shfl_xor_sync(0xffffffffu, sq, o);
    }
    float mu = sum * (1.0f / HH);
    float var = sq * (1.0f / HH) - mu * mu;
    float inv = rsqrtf(var + EPSL);
    float* q = out + (size_t)row * HH;
#pragma unroll
    for (int i = 0; i < HH / 32; i++) {
        int c = lane + i * 32;
        q[c] = roundtf(g[c] * (p[c] - mu) * inv + beta[c]);
    }
}

// ---------------- attention (flash-style, tf32-rounded out) ----------------
__global__ __launch_bounds__(128) void attention_kernel(
    const float* __restrict__ qkv, float* __restrict__ o) {
    const int qt = blockIdx.x;
    const int h = blockIdx.y;
    const int b = blockIdx.z;
    __shared__ float Qs[32][HD + 1];
    __shared__ float Kst[HD][64];
    __shared__ float Vs[64][HD];
    const int tid = threadIdx.x;
    const int r = tid >> 2;
    const int part = tid & 3;
    const int lane = tid & 31;
    const size_t base = (size_t)b * SS * 3 * HH;

    for (int i = tid; i < 32 * 16; i += 128) {
        int row = i >> 4, d4 = (i & 15) * 4;
        float4 v = *(const float4*)(qkv + base + (size_t)(qt * 32 + row) * 3 * HH + h * HD + d4);
        Qs[row][d4 + 0] = v.x; Qs[row][d4 + 1] = v.y;
        Qs[row][d4 + 2] = v.z; Qs[row][d4 + 3] = v.w;
    }

    float acc[16];
#pragma unroll
    for (int i = 0; i < 16; i++) acc[i] = 0.f;
    float m = -1e30f, l = 0.f;

    for (int kt = 0; kt < SS; kt += 64) {
        __syncthreads();
        for (int i = tid; i < 64 * 16; i += 128) {
            int row = i >> 4, d4 = (i & 15) * 4;
            const float* kp = qkv + base + (size_t)(kt + row) * 3 * HH + HH + h * HD + d4;
            float4 kv = *(const float4*)kp;
            Kst[d4 + 0][row] = kv.x; Kst[d4 + 1][row] = kv.y;
            Kst[d4 + 2][row] = kv.z; Kst[d4 + 3][row] = kv.w;
            *(float4*)&Vs[row][d4] = *(const float4*)(kp + HH);
        }
        __syncthreads();

        float sc[16];
#pragma unroll
        for (int jj = 0; jj < 16; jj++) sc[jj] = 0.f;
        for (int d = 0; d < HD; ++d) {
            float qv = Qs[r][d];
            const float* kr = &Kst[d][part * 16];
#pragma unroll
            for (int jj = 0; jj < 16; jj++) sc[jj] += qv * kr[jj];
        }
        float tmax = -1e30f;
#pragma unroll
        for (int jj = 0; jj < 16; jj++) { sc[jj] *= 0.125f; tmax = fmaxf(tmax, sc[jj]); }
        tmax = fmaxf(tmax, __shfl_xor_sync(0xffffffffu, tmax, 1));
        tmax = fmaxf(tmax, __shfl_xor_sync(0xffffffffu, tmax, 2));
        float mnew = fmaxf(m, tmax);
        float corr = __expf(m - mnew);
        float pl[16];
        float psum = 0.f;
#pragma unroll
        for (int jj = 0; jj < 16; jj++) { pl[jj] = __expf(sc[jj] - mnew); psum += pl[jj]; }
        psum += __shfl_xor_sync(0xffffffffu, psum, 1);
        psum += __shfl_xor_sync(0xffffffffu, psum, 2);
        l = l * corr + psum;
        m = mnew;
#pragma unroll
        for (int i = 0; i < 16; i++) acc[i] *= corr;
#pragma unroll
        for (int src = 0; src < 4; ++src) {
#pragma unroll
            for (int jj = 0; jj < 16; jj++) {
                float p = __shfl_sync(0xffffffffu, pl[jj], (lane & ~3) | src);
                const float* vr = &Vs[src * 16 + jj][part * 16];
#pragma unroll
                for (int dd = 0; dd < 16; dd++) acc[dd] += p * vr[dd];
            }
        }
    }
    float linv = 1.f / l;
    float* op = o + (size_t)(b * SS + qt * 32 + r) * HH + h * HD + part * 16;
#pragma unroll
    for (int dd = 0; dd < 16; dd++) op[dd] = roundtf(acc[dd] * linv);
}

// ---------------- launch ----------------
extern "C" void kernel_launch(void* const* d_in, const int* in_sizes, int n_in,
                              void* d_out, int out_size) {
    const int*   tokens = (const int*)d_in[0];
    const float* emb    = (const float*)d_in[1];
    const float* W0     = (const float*)d_in[2];
    const float* b0     = (const float*)d_in[3];
    const float* tau0   = (const float*)d_in[4];
    const float* g0     = (const float*)d_in[5];
    const float* be0    = (const float*)d_in[6];
    const float* W1     = (const float*)d_in[7];
    const float* b1     = (const float*)d_in[8];
    const float* tau1   = (const float*)d_in[9];
    const float* g1     = (const float*)d_in[10];
    const float* be1    = (const float*)d_in[11];
    const float* w_in   = (const float*)d_in[12];
    const float* b_in   = (const float*)d_in[13];
    const float* w_o    = (const float*)d_in[14];
    const float* b_o    = (const float*)d_in[15];
    const float* Wout   = (const float*)d_in[16];
    const float* bout   = (const float*)d_in[17];
    const float* log_dt = (const float*)d_in[18];
    float* out = (float*)d_out;

    float *px, *pI, *pact, *pqkv, *po, *pw0, *pw1, *pwin, *pwo, *pwout;
    cudaGetSymbolAddress((void**)&px,    g_x);
    cudaGetSymbolAddress((void**)&pI,    g_I);
    cudaGetSymbolAddress((void**)&pact,  g_act);
    cudaGetSymbolAddress((void**)&pqkv,  g_qkv);
    cudaGetSymbolAddress((void**)&po,    g_o);
    cudaGetSymbolAddress((void**)&pw0,   g_w0);
    cudaGetSymbolAddress((void**)&pw1,   g_w1);
    cudaGetSymbolAddress((void**)&pwin,  g_win);
    cudaGetSymbolAddress((void**)&pwo,   g_wo);
    cudaGetSymbolAddress((void**)&pwout, g_wout);

    cudaFuncSetAttribute(gemm_tf32, cudaFuncAttributeMaxDynamicSharedMemorySize, GEMM_SMEM);

    const int M = BB * SS;  // 4096

    // launch order chosen so launch #5 (ncu -s 5) is a gemm_tf32 instance
    embed_pos_kernel<<<(BB * SS * EE) / 256, 256>>>(tokens, emb, px);                       // 0
    round_tf32_kernel<<<(HH * EE / 4 + 255) / 256, 256>>>(W0, pw0, HH * EE / 4);           // 1
    round_tf32_kernel<<<(HH * HH / 4 + 255) / 256, 256>>>(W1, pw1, HH * HH / 4);           // 2
    round_tf32_kernel<<<(3 * HH * HH / 4 + 255) / 256, 256>>>(w_in, pwin, 3 * HH * HH / 4);// 3
    round_tf32_kernel<<<(HH * HH / 4 + 255) / 256, 256>>>(w_o, pwo, HH * HH / 4);          // 4

    gemm_tf32<<<dim3(M / 128, HH / 128), 256, GEMM_SMEM>>>(px, pw0, b0, pI, M, HH, EE, 0); // 5 <- profiled
    liquid_scan_kernel<<<(BB * HH + 255) / 256, 256>>>(pI, tau0, log_dt, pact);
    layernorm_kernel<<<M / 8, 256>>>(pact, g0, be0, px);

    gemm_tf32<<<dim3(M / 128, HH / 128), 256, GEMM_SMEM>>>(px, pw1, b1, pI, M, HH, HH, 0);
    liquid_scan_kernel<<<(BB * HH + 255) / 256, 256>>>(pI, tau1, log_dt, pact);
    layernorm_kernel<<<M / 8, 256>>>(pact, g1, be1, px);

    gemm_tf32<<<dim3(M / 128, 3 * HH / 128), 256, GEMM_SMEM>>>(px, pwin, b_in, pqkv, M, 3 * HH, HH, 0);
    attention_kernel<<<dim3(SS / 32, NHH, BB), 128>>>(pqkv, po);
    gemm_tf32<<<dim3(M / 128, HH / 128), 256, GEMM_SMEM>>>(po, pwo, b_o, px, M, HH, HH, 1);

    round_tf32_kernel<<<(VV * HH / 4 + 255) / 256, 256>>>(Wout, pwout, VV * HH / 4);
    gemm_tf32<<<dim3(M / 128, VV / 128), 256, GEMM_SMEM>>>(px, pwout, bout, out, M, VV, HH, 0);
}